// round 9
// baseline (speedup 1.0000x reference)
#include <cuda_runtime.h>
#include <cuda_bf16.h>

// Problem constants
#define BATCH 16
#define NPTS 2048              // N == M == 2048
#define NPAIRS (NPTS / 2)      // 1024 packed target pairs
#define NUM_CLASSES 40
#define THREADS 256
#define QCHUNKS 16             // 128 queries per block
#define NBLOCKS (2 * BATCH * QCHUNKS)   // 512
#define QPB 128                // queries per block (32 lanes x 4 per thread)
#define NGROUPS 8              // target-groups per block
#define PAIRS_PER_GROUP (NPAIRS / NGROUPS)  // 128

// Deterministic scratch (no device allocation allowed)
__device__ float g_partials[NBLOCKS];
__device__ int   g_count = 0;   // self-resetting completion counter

// Packed f32x2 helpers (sm_103a FFMA2 — only reachable via PTX)
#define FMA2(acc, a, b) \
    asm("fma.rn.f32x2 %0, %1, %2, %0;" : "+l"(acc) : "l"(a), "l"(b))
#define PACK_REP(dst, s) \
    asm("mov.b64 %0, {%1, %1};" : "=l"(dst) : "f"(s))
#define UNPACK2(lo, hi, src) \
    asm("mov.b64 {%0, %1}, %2;" : "=f"(lo), "=f"(hi) : "l"(src))

// One block: (direction, batch, chunk-of-128-queries).
// 256 threads = 32 query-lanes x 8 target-groups. Thread (lane, grp) owns
// queries q = chunk*128 + lane + s*32 (s=0..3) and scans target-group grp
// (128 of 1024 pairs). Four independent FFMA2 chains per LDS pair.
// Query norms are recomputed AFTER the loop from the packed -2x regs to
// keep loop-carried registers <= 64 (occupancy 4 blocks/SM).
// SMEM target tile, pair-interleaved SoA:
//   sA[p] = (x_{2p}, x_{2p+1}, y_{2p}, y_{2p+1})
//   sB[p] = (z_{2p}, z_{2p+1}, w_{2p}, w_{2p+1})   w = |y|^2
// d(x,y) = |x|^2 + (w - 2 x.y); -2 folded into packed query regs.
__global__ __launch_bounds__(THREADS, 4)
void chamfer_kernel(const float* __restrict__ reg,
                    const float* __restrict__ p1,
                    const float* __restrict__ pred,
                    const int*   __restrict__ target32,
                    float* __restrict__ out) {
    __shared__ float4 sA[NPAIRS];          // 16 KB
    __shared__ float4 sB[NPAIRS];          // 16 KB
    __shared__ float  smin[4][THREADS];    // 4 KB per-thread mins per query slot
    __shared__ float  sred[64];
    __shared__ int    s_last;

    const int blk   = blockIdx.x;
    const int dir   = blk >> 8;          // 512 blocks: bit 8 = direction
    const int rem   = blk & 255;
    const int b     = rem >> 4;
    const int chunk = rem & 15;
    const int tid   = threadIdx.x;
    const int lane  = tid & 31;          // query lane 0..31
    const int grp   = tid >> 5;          // target group 0..7

    const float* __restrict__ xsrc = dir ? p1 : reg;
    const float* __restrict__ ysrc = dir ? reg : p1;
    const float* xb = xsrc + (size_t)b * NPTS * 3;
    const float* yb = ysrc + (size_t)b * NPTS * 3;

    // Fill pair-interleaved SoA tile, precompute |y|^2 (4 pairs per thread)
    for (int p = tid; p < NPAIRS; p += THREADS) {
        const float a0 = yb[6 * p + 0], a1 = yb[6 * p + 1], a2 = yb[6 * p + 2];
        const float b0 = yb[6 * p + 3], b1 = yb[6 * p + 4], b2 = yb[6 * p + 5];
        sA[p] = make_float4(a0, b0, a1, b1);
        sB[p] = make_float4(a2, b2,
                            a0 * a0 + a1 * a1 + a2 * a2,
                            b0 * b0 + b1 * b1 + b2 * b2);
    }
    __syncthreads();

    // 4 query points per thread; only the packed -2*coord regs stay live
    const int qbase = chunk * QPB + lane;
    unsigned long long X[4], Y[4], Z[4];
    #pragma unroll
    for (int s = 0; s < 4; s++) {
        const int q = qbase + 32 * s;
        PACK_REP(X[s], -2.0f * xb[q * 3 + 0]);
        PACK_REP(Y[s], -2.0f * xb[q * 3 + 1]);
        PACK_REP(Z[s], -2.0f * xb[q * 3 + 2]);
    }

    const ulonglong2* __restrict__ pA = reinterpret_cast<const ulonglong2*>(sA);
    const ulonglong2* __restrict__ pB = reinterpret_cast<const ulonglong2*>(sB);

    // Split min accumulators (lo/hi lane) per query slot
    float ma[4] = {3.0e38f, 3.0e38f, 3.0e38f, 3.0e38f};
    float mb[4] = {3.0e38f, 3.0e38f, 3.0e38f, 3.0e38f};

    const int pbeg = grp * PAIRS_PER_GROUP;
    #pragma unroll 2
    for (int p = pbeg; p < pbeg + PAIRS_PER_GROUP; p++) {
        const ulonglong2 qa = pA[p];   // .x = xpair, .y = ypair
        const ulonglong2 qb = pB[p];   // .x = zpair, .y = wpair
        #pragma unroll
        for (int s = 0; s < 4; s++) {
            unsigned long long t = qb.y;    // acc = {w_j, w_j+1}
            FMA2(t, X[s], qa.x);
            FMA2(t, Y[s], qa.y);
            FMA2(t, Z[s], qb.x);
            float lo, hi; UNPACK2(lo, hi, t);
            ma[s] = fminf(ma[s], lo);
            mb[s] = fminf(mb[s], hi);
        }
    }

    #pragma unroll
    for (int s = 0; s < 4; s++)
        smin[s][tid] = fminf(ma[s], mb[s]);
    __syncthreads();

    // Recover query norms from packed -2x regs: n = 0.25*(x^2+y^2+z^2)
    float n[4];
    #pragma unroll
    for (int s = 0; s < 4; s++) {
        float xl, xh, yl, yh, zl, zh;
        UNPACK2(xl, xh, X[s]);
        UNPACK2(yl, yh, Y[s]);
        UNPACK2(zl, zh, Z[s]);
        (void)xh; (void)yh; (void)zh;
        n[s] = 0.25f * (xl * xl + yl * yl + zl * zl);
    }

    // Combine the 8 groups per (lane, slot): warp 0 does it (owns same queries)
    if (tid < 32) {
        float acc = 0.0f;
        #pragma unroll
        for (int s = 0; s < 4; s++) {
            float m = smin[s][lane];
            #pragma unroll
            for (int g = 1; g < NGROUPS; g++)
                m = fminf(m, smin[s][32 * g + lane]);
            acc += n[s] + m;
        }
        float v = acc;
        #pragma unroll
        for (int off = 16; off > 0; off >>= 1)
            v += __shfl_down_sync(0xFFFFFFFFu, v, off);
        if (tid == 0) g_partials[blk] = v;
    }

    // Fused finalize: last block to finish sums partials + NLL.
    if (tid == 0) {
        __threadfence();
        const int r = atomicAdd(&g_count, 1);
        s_last = (r == NBLOCKS - 1);
    }
    __syncthreads();
    if (!s_last) return;
    __threadfence();   // acquire: make other blocks' partials visible

    // 512 partials, 256 threads: 2 each (volatile reload), warp-level finish
    float w;
    {
        volatile float* vp = g_partials;
        w = vp[tid] + vp[tid + THREADS];
    }
    {
        #pragma unroll
        for (int off = 16; off > 0; off >>= 1)
            w += __shfl_down_sync(0xFFFFFFFFu, w, off);
        if ((tid & 31) == 0) sred[tid >> 5] = w;
    }
    __syncthreads();
    if (tid == 0) {
        float tot = 0.0f;
        #pragma unroll
        for (int i = 0; i < THREADS / 32; i++) tot += sred[i];
        const float reg_loss = tot / (float)(BATCH * NPTS);

        // dtype sniff: JAX x64-disabled emits int32 despite declared int64.
        // int64 iff all odd 32-bit words of the 16 entries are zero
        // (false-positive prob with int32 targets in [0,40): 40^-8 ~ 0).
        bool is64 = true;
        #pragma unroll
        for (int i = 0; i < 8; i++)
            if (target32[2 * i + 1] != 0) is64 = false;

        float nll = 0.0f;
        #pragma unroll
        for (int i = 0; i < BATCH; i++) {
            int t = is64 ? target32[2 * i] : target32[i];
            t = (t < 0) ? 0 : (t >= NUM_CLASSES ? NUM_CLASSES - 1 : t);
            nll -= pred[i * NUM_CLASSES + t];
        }
        nll /= (float)BATCH;
        out[0] = nll + reg_loss;
        g_count = 0;   // self-reset for next graph replay
    }
}

extern "C" void kernel_launch(void* const* d_in, const int* in_sizes, int n_in,
                              void* d_out, int out_size) {
    const float* reg    = (const float*)d_in[0];   // [16, 2048, 3]
    const float* p1     = (const float*)d_in[1];   // [16, 2048, 3]
    const float* pred   = (const float*)d_in[2];   // [16, 40] log-probs
    const int*   target = (const int*)d_in[3];     // [16] int32 (or int64, sniffed)
    float* out = (float*)d_out;

    chamfer_kernel<<<NBLOCKS, THREADS>>>(reg, p1, pred, target, out);
}

// round 10
// speedup vs baseline: 1.0087x; 1.0087x over previous
#include <cuda_runtime.h>
#include <cuda_bf16.h>

// Problem constants
#define BATCH 16
#define NPTS 2048              // N == M == 2048
#define NPAIRS (NPTS / 2)      // 1024 packed target pairs
#define NUM_CLASSES 40
#define THREADS 256
#define QCHUNKS 32             // 64 queries per block
#define NBLOCKS (2 * BATCH * QCHUNKS)   // 1024
#define QPB 64                 // queries per block (32 lanes x 2 per thread)
#define NGROUPS 8              // target-groups per block
#define PAIRS_PER_GROUP (NPAIRS / NGROUPS)  // 128

// Deterministic scratch (no device allocation allowed)
__device__ float g_partials[NBLOCKS];
__device__ int   g_count = 0;   // self-resetting completion counter

// Packed f32x2 helpers (sm_103a FFMA2 — only reachable via PTX)
#define FMA2(acc, a, b) \
    asm("fma.rn.f32x2 %0, %1, %2, %0;" : "+l"(acc) : "l"(a), "l"(b))
#define PACK_REP(dst, s) \
    asm("mov.b64 %0, {%1, %1};" : "=l"(dst) : "f"(s))
#define UNPACK2(lo, hi, src) \
    asm("mov.b64 {%0, %1}, %2;" : "=f"(lo), "=f"(hi) : "l"(src))

// One block: (direction, batch, chunk-of-64-queries) — full-cloud scan, so
// the per-query min is complete within the block (partials stay summable).
// 256 threads = 32 query-lanes x 8 target-groups. Thread (lane, grp) owns
// queries q = chunk*64 + lane + s*32 (s=0..1), scans target-group grp
// (128 of 1024 pairs). Finer 1024-block grid streams through ~5 blocks/SM
// for high sustained residency (the R9 single-wave grid stalled at occ 33%).
// SMEM target tile, pair-interleaved SoA:
//   sA[p] = (x_{2p}, x_{2p+1}, y_{2p}, y_{2p+1})
//   sB[p] = (z_{2p}, z_{2p+1}, w_{2p}, w_{2p+1})   w = |y|^2
// d(x,y) = |x|^2 + (w - 2 x.y); -2 folded into packed query regs.
__global__ __launch_bounds__(THREADS, 5)
void chamfer_kernel(const float* __restrict__ reg,
                    const float* __restrict__ p1,
                    const float* __restrict__ pred,
                    const int*   __restrict__ target32,
                    float* __restrict__ out) {
    __shared__ float4 sA[NPAIRS];          // 16 KB
    __shared__ float4 sB[NPAIRS];          // 16 KB
    __shared__ float  smin[2][THREADS];    // 2 KB per-thread mins per query slot
    __shared__ float  sred[8];
    __shared__ int    s_last;

    const int blk   = blockIdx.x;
    const int dir   = blk >> 9;          // 1024 blocks: bit 9 = direction
    const int rem   = blk & 511;
    const int b     = rem >> 5;
    const int chunk = rem & 31;
    const int tid   = threadIdx.x;
    const int lane  = tid & 31;          // query lane 0..31
    const int grp   = tid >> 5;          // target group 0..7

    const float* __restrict__ xsrc = dir ? p1 : reg;
    const float* __restrict__ ysrc = dir ? reg : p1;
    const float* xb = xsrc + (size_t)b * NPTS * 3;
    const float* yb = ysrc + (size_t)b * NPTS * 3;

    // Fill pair-interleaved SoA tile, precompute |y|^2 (4 pairs per thread)
    for (int p = tid; p < NPAIRS; p += THREADS) {
        const float a0 = yb[6 * p + 0], a1 = yb[6 * p + 1], a2 = yb[6 * p + 2];
        const float b0 = yb[6 * p + 3], b1 = yb[6 * p + 4], b2 = yb[6 * p + 5];
        sA[p] = make_float4(a0, b0, a1, b1);
        sB[p] = make_float4(a2, b2,
                            a0 * a0 + a1 * a1 + a2 * a2,
                            b0 * b0 + b1 * b1 + b2 * b2);
    }
    __syncthreads();

    // 2 query points per thread; only the packed -2*coord regs stay live
    const int qbase = chunk * QPB + lane;
    unsigned long long X[2], Y[2], Z[2];
    #pragma unroll
    for (int s = 0; s < 2; s++) {
        const int q = qbase + 32 * s;
        PACK_REP(X[s], -2.0f * xb[q * 3 + 0]);
        PACK_REP(Y[s], -2.0f * xb[q * 3 + 1]);
        PACK_REP(Z[s], -2.0f * xb[q * 3 + 2]);
    }

    const ulonglong2* __restrict__ pA = reinterpret_cast<const ulonglong2*>(sA);
    const ulonglong2* __restrict__ pB = reinterpret_cast<const ulonglong2*>(sB);

    // Split min accumulators (lo/hi lane) per query slot
    float ma[2] = {3.0e38f, 3.0e38f};
    float mb[2] = {3.0e38f, 3.0e38f};

    const int pbeg = grp * PAIRS_PER_GROUP;
    #pragma unroll 4
    for (int p = pbeg; p < pbeg + PAIRS_PER_GROUP; p++) {
        const ulonglong2 qa = pA[p];   // .x = xpair, .y = ypair
        const ulonglong2 qb = pB[p];   // .x = zpair, .y = wpair
        #pragma unroll
        for (int s = 0; s < 2; s++) {
            unsigned long long t = qb.y;    // acc = {w_j, w_j+1}
            FMA2(t, X[s], qa.x);
            FMA2(t, Y[s], qa.y);
            FMA2(t, Z[s], qb.x);
            float lo, hi; UNPACK2(lo, hi, t);
            ma[s] = fminf(ma[s], lo);
            mb[s] = fminf(mb[s], hi);
        }
    }

    #pragma unroll
    for (int s = 0; s < 2; s++)
        smin[s][tid] = fminf(ma[s], mb[s]);
    __syncthreads();

    // Recover query norms from packed -2x regs: n = 0.25*(x^2+y^2+z^2)
    // (valid on the group-0 threads that do the combine: same queries)
    float n[2];
    #pragma unroll
    for (int s = 0; s < 2; s++) {
        float xl, xh, yl, yh, zl, zh;
        UNPACK2(xl, xh, X[s]);
        UNPACK2(yl, yh, Y[s]);
        UNPACK2(zl, zh, Z[s]);
        (void)xh; (void)yh; (void)zh;
        n[s] = 0.25f * (xl * xl + yl * yl + zl * zl);
    }

    // Combine the 8 groups per (lane, slot): warp 0 does it (owns same queries)
    if (tid < 32) {
        float acc = 0.0f;
        #pragma unroll
        for (int s = 0; s < 2; s++) {
            float m = smin[s][lane];
            #pragma unroll
            for (int g = 1; g < NGROUPS; g++)
                m = fminf(m, smin[s][32 * g + lane]);
            acc += n[s] + m;
        }
        float v = acc;
        #pragma unroll
        for (int off = 16; off > 0; off >>= 1)
            v += __shfl_down_sync(0xFFFFFFFFu, v, off);
        if (tid == 0) g_partials[blk] = v;
    }

    // Fused finalize: last block to finish sums partials + NLL.
    if (tid == 0) {
        __threadfence();
        const int r = atomicAdd(&g_count, 1);
        s_last = (r == NBLOCKS - 1);
    }
    __syncthreads();
    if (!s_last) return;
    __threadfence();   // acquire: make other blocks' partials visible

    // 1024 partials, 256 threads: 4 each (volatile reload), warp-level finish
    float w;
    {
        volatile float* vp = g_partials;
        w = (vp[tid] + vp[tid + THREADS])
          + (vp[tid + 2 * THREADS] + vp[tid + 3 * THREADS]);
    }
    {
        #pragma unroll
        for (int off = 16; off > 0; off >>= 1)
            w += __shfl_down_sync(0xFFFFFFFFu, w, off);
        if ((tid & 31) == 0) sred[tid >> 5] = w;
    }
    __syncthreads();
    if (tid == 0) {
        float tot = 0.0f;
        #pragma unroll
        for (int i = 0; i < THREADS / 32; i++) tot += sred[i];
        const float reg_loss = tot / (float)(BATCH * NPTS);

        // dtype sniff: JAX x64-disabled emits int32 despite declared int64.
        // int64 iff all odd 32-bit words of the 16 entries are zero
        // (false-positive prob with int32 targets in [0,40): 40^-8 ~ 0).
        bool is64 = true;
        #pragma unroll
        for (int i = 0; i < 8; i++)
            if (target32[2 * i + 1] != 0) is64 = false;

        float nll = 0.0f;
        #pragma unroll
        for (int i = 0; i < BATCH; i++) {
            int t = is64 ? target32[2 * i] : target32[i];
            t = (t < 0) ? 0 : (t >= NUM_CLASSES ? NUM_CLASSES - 1 : t);
            nll -= pred[i * NUM_CLASSES + t];
        }
        nll /= (float)BATCH;
        out[0] = nll + reg_loss;
        g_count = 0;   // self-reset for next graph replay
    }
}

extern "C" void kernel_launch(void* const* d_in, const int* in_sizes, int n_in,
                              void* d_out, int out_size) {
    const float* reg    = (const float*)d_in[0];   // [16, 2048, 3]
    const float* p1     = (const float*)d_in[1];   // [16, 2048, 3]
    const float* pred   = (const float*)d_in[2];   // [16, 40] log-probs
    const int*   target = (const int*)d_in[3];     // [16] int32 (or int64, sniffed)
    float* out = (float*)d_out;

    chamfer_kernel<<<NBLOCKS, THREADS>>>(reg, p1, pred, target, out);
}

// round 11
// speedup vs baseline: 1.0943x; 1.0849x over previous
#include <cuda_runtime.h>
#include <cuda_bf16.h>

// Problem constants
#define BATCH 16
#define NPTS 2048              // N == M == 2048
#define NPAIRS (NPTS / 2)      // 1024 packed target pairs
#define NUM_CLASSES 40
#define THREADS 256
#define QCHUNKS 16             // 128 queries per block
#define NBLOCKS (2 * BATCH * QCHUNKS)   // 512
#define QPB 128                // queries per block (32 lanes x 4 per thread)
#define NGROUPS 8              // target-groups per block
#define PAIRS_PER_GROUP (NPAIRS / NGROUPS)  // 128

// Deterministic scratch (no device allocation allowed)
__device__ float g_partials[NBLOCKS];
__device__ int   g_count = 0;   // self-resetting completion counter

// Packed f32x2 helpers (sm_103a FFMA2 — only reachable via PTX)
#define FMA2(acc, a, b) \
    asm("fma.rn.f32x2 %0, %1, %2, %0;" : "+l"(acc) : "l"(a), "l"(b))
#define PACK_REP(dst, s) \
    asm("mov.b64 %0, {%1, %1};" : "=l"(dst) : "f"(s))
#define UNPACK2(lo, hi, src) \
    asm("mov.b64 {%0, %1}, %2;" : "=f"(lo), "=f"(hi) : "l"(src))

// One block: (direction, batch, chunk-of-128-queries) — full-cloud scan, so
// the per-query min is complete within the block (partials stay summable).
// 256 threads = 32 query-lanes x 8 target-groups. Thread (lane, grp) owns
// queries q = chunk*128 + lane + s*32 (s=0..3), scans target-group grp
// (128 of 1024 pairs). 4 slots amortize each LDS.128 over 8 q-t distances
// (keeps the L1 crossbar ~30% — the R10 2-slot config queued at 60%).
// Single min accumulator per slot + norm-recompute keep live regs <= 64
// so 4 blocks/SM stay resident; unroll 4 batches 8 LDS for MLP.
// SMEM target tile, pair-interleaved SoA:
//   sA[p] = (x_{2p}, x_{2p+1}, y_{2p}, y_{2p+1})
//   sB[p] = (z_{2p}, z_{2p+1}, w_{2p}, w_{2p+1})   w = |y|^2
// d(x,y) = |x|^2 + (w - 2 x.y); -2 folded into packed query regs.
__global__ __launch_bounds__(THREADS, 4)
void chamfer_kernel(const float* __restrict__ reg,
                    const float* __restrict__ p1,
                    const float* __restrict__ pred,
                    const int*   __restrict__ target32,
                    float* __restrict__ out) {
    __shared__ float4 sA[NPAIRS];          // 16 KB
    __shared__ float4 sB[NPAIRS];          // 16 KB
    __shared__ float  smin[4][THREADS];    // 4 KB per-thread mins per query slot
    __shared__ float  sred[8];
    __shared__ int    s_last;

    const int blk   = blockIdx.x;
    const int dir   = blk >> 8;          // 512 blocks: bit 8 = direction
    const int rem   = blk & 255;
    const int b     = rem >> 4;
    const int chunk = rem & 15;
    const int tid   = threadIdx.x;
    const int lane  = tid & 31;          // query lane 0..31
    const int grp   = tid >> 5;          // target group 0..7

    const float* __restrict__ xsrc = dir ? p1 : reg;
    const float* __restrict__ ysrc = dir ? reg : p1;
    const float* xb = xsrc + (size_t)b * NPTS * 3;
    const float* yb = ysrc + (size_t)b * NPTS * 3;

    // Fill pair-interleaved SoA tile, precompute |y|^2 (4 pairs per thread)
    for (int p = tid; p < NPAIRS; p += THREADS) {
        const float a0 = yb[6 * p + 0], a1 = yb[6 * p + 1], a2 = yb[6 * p + 2];
        const float b0 = yb[6 * p + 3], b1 = yb[6 * p + 4], b2 = yb[6 * p + 5];
        sA[p] = make_float4(a0, b0, a1, b1);
        sB[p] = make_float4(a2, b2,
                            a0 * a0 + a1 * a1 + a2 * a2,
                            b0 * b0 + b1 * b1 + b2 * b2);
    }
    __syncthreads();

    // 4 query points per thread; only the packed -2*coord regs stay live
    const int qbase = chunk * QPB + lane;
    unsigned long long X[4], Y[4], Z[4];
    #pragma unroll
    for (int s = 0; s < 4; s++) {
        const int q = qbase + 32 * s;
        PACK_REP(X[s], -2.0f * xb[q * 3 + 0]);
        PACK_REP(Y[s], -2.0f * xb[q * 3 + 1]);
        PACK_REP(Z[s], -2.0f * xb[q * 3 + 2]);
    }

    const ulonglong2* __restrict__ pA = reinterpret_cast<const ulonglong2*>(sA);
    const ulonglong2* __restrict__ pB = reinterpret_cast<const ulonglong2*>(sB);

    // One min accumulator per query slot (4 parallel chains cover FMNMX lat)
    float m[4] = {3.0e38f, 3.0e38f, 3.0e38f, 3.0e38f};

    const int pbeg = grp * PAIRS_PER_GROUP;
    #pragma unroll 4
    for (int p = pbeg; p < pbeg + PAIRS_PER_GROUP; p++) {
        const ulonglong2 qa = pA[p];   // .x = xpair, .y = ypair
        const ulonglong2 qb = pB[p];   // .x = zpair, .y = wpair
        #pragma unroll
        for (int s = 0; s < 4; s++) {
            unsigned long long t = qb.y;    // acc = {w_j, w_j+1}
            FMA2(t, X[s], qa.x);
            FMA2(t, Y[s], qa.y);
            FMA2(t, Z[s], qb.x);
            float lo, hi; UNPACK2(lo, hi, t);
            m[s] = fminf(m[s], fminf(lo, hi));
        }
    }

    #pragma unroll
    for (int s = 0; s < 4; s++)
        smin[s][tid] = m[s];
    __syncthreads();

    // Recover query norms from packed -2x regs: n = 0.25*(x^2+y^2+z^2)
    // (valid on the group-0 threads that do the combine: same queries)
    float n[4];
    #pragma unroll
    for (int s = 0; s < 4; s++) {
        float xl, xh, yl, yh, zl, zh;
        UNPACK2(xl, xh, X[s]);
        UNPACK2(yl, yh, Y[s]);
        UNPACK2(zl, zh, Z[s]);
        (void)xh; (void)yh; (void)zh;
        n[s] = 0.25f * (xl * xl + yl * yl + zl * zl);
    }

    // Combine the 8 groups per (lane, slot): warp 0 does it (owns same queries)
    if (tid < 32) {
        float acc = 0.0f;
        #pragma unroll
        for (int s = 0; s < 4; s++) {
            float mm = smin[s][lane];
            #pragma unroll
            for (int g = 1; g < NGROUPS; g++)
                mm = fminf(mm, smin[s][32 * g + lane]);
            acc += n[s] + mm;
        }
        float v = acc;
        #pragma unroll
        for (int off = 16; off > 0; off >>= 1)
            v += __shfl_down_sync(0xFFFFFFFFu, v, off);
        if (tid == 0) g_partials[blk] = v;
    }

    // Fused finalize: last block to finish sums partials + NLL.
    if (tid == 0) {
        __threadfence();
        const int r = atomicAdd(&g_count, 1);
        s_last = (r == NBLOCKS - 1);
    }
    __syncthreads();
    if (!s_last) return;
    __threadfence();   // acquire: make other blocks' partials visible

    // 512 partials, 256 threads: 2 each (volatile reload), warp-level finish
    float w;
    {
        volatile float* vp = g_partials;
        w = vp[tid] + vp[tid + THREADS];
    }
    {
        #pragma unroll
        for (int off = 16; off > 0; off >>= 1)
            w += __shfl_down_sync(0xFFFFFFFFu, w, off);
        if ((tid & 31) == 0) sred[tid >> 5] = w;
    }
    __syncthreads();
    if (tid == 0) {
        float tot = 0.0f;
        #pragma unroll
        for (int i = 0; i < THREADS / 32; i++) tot += sred[i];
        const float reg_loss = tot / (float)(BATCH * NPTS);

        // dtype sniff: JAX x64-disabled emits int32 despite declared int64.
        // int64 iff all odd 32-bit words of the 16 entries are zero
        // (false-positive prob with int32 targets in [0,40): 40^-8 ~ 0).
        bool is64 = true;
        #pragma unroll
        for (int i = 0; i < 8; i++)
            if (target32[2 * i + 1] != 0) is64 = false;

        float nll = 0.0f;
        #pragma unroll
        for (int i = 0; i < BATCH; i++) {
            int t = is64 ? target32[2 * i] : target32[i];
            t = (t < 0) ? 0 : (t >= NUM_CLASSES ? NUM_CLASSES - 1 : t);
            nll -= pred[i * NUM_CLASSES + t];
        }
        nll /= (float)BATCH;
        out[0] = nll + reg_loss;
        g_count = 0;   // self-reset for next graph replay
    }
}

extern "C" void kernel_launch(void* const* d_in, const int* in_sizes, int n_in,
                              void* d_out, int out_size) {
    const float* reg    = (const float*)d_in[0];   // [16, 2048, 3]
    const float* p1     = (const float*)d_in[1];   // [16, 2048, 3]
    const float* pred   = (const float*)d_in[2];   // [16, 40] log-probs
    const int*   target = (const int*)d_in[3];     // [16] int32 (or int64, sniffed)
    float* out = (float*)d_out;

    chamfer_kernel<<<NBLOCKS, THREADS>>>(reg, p1, pred, target, out);
}